// round 17
// baseline (speedup 1.0000x reference)
#include <cuda_runtime.h>
#include <cuda_bf16.h>
#include <cuda_fp16.h>
#include <cstdint>
#include <math.h>

#define SEQ  4096
#define HID  2304
#define NH   8
#define NKV  4
#define HD   256

// ---------------- scratch (no allocation allowed) ----------------
// QKV fp32 output, head-split: heads 0-7 = Q, 8-11 = K, 12-15 = V
__device__ float  g_QKV[16 * SEQ * HD];
__device__ float2 g_rope[SEQ * 128];
// fp16 GEMM operand buffers (A: Hf, then fp16 ctx written by flash; B: weights^T)
__device__ __half g_Af[SEQ * HID];
__device__ __half g_Bf[4096 * HID];
// fp16 attention operands
__device__ __half g_Qf[NH  * SEQ * HD];   // [h][s][d]
__device__ __half g_Kf[NKV * SEQ * HD];   // [kvh][s][d]
__device__ __half g_Vt[NKV * HD * SEQ];   // [kvh][d][s]

// ================= PTX helpers (sm_103-neutral) =================
__device__ __forceinline__ uint32_t smem_u32(const void* p) {
    uint32_t a;
    asm("{ .reg .u64 t; cvta.to.shared.u64 t, %1; cvt.u32.u64 %0, t; }" : "=r"(a) : "l"(p));
    return a;
}
__device__ __forceinline__ void cp16(uint32_t s, const void* g) {
    asm volatile("cp.async.cg.shared.global [%0], [%1], 16;" :: "r"(s), "l"(g));
}
#define CP_COMMIT() asm volatile("cp.async.commit_group;" ::: "memory")
#define CP_WAIT1()  asm volatile("cp.async.wait_group 1;" ::: "memory")
#define CP_WAIT0()  asm volatile("cp.async.wait_group 0;" ::: "memory")

__device__ __forceinline__ void ldsm4(uint32_t* r, uint32_t a) {
    asm volatile("ldmatrix.sync.aligned.m8n8.x4.shared.b16 {%0,%1,%2,%3}, [%4];"
                 : "=r"(r[0]), "=r"(r[1]), "=r"(r[2]), "=r"(r[3]) : "r"(a));
}
__device__ __forceinline__ void mma16816h(float* c, const uint32_t* a, const uint32_t* b) {
    asm volatile(
        "mma.sync.aligned.m16n8k16.row.col.f32.f16.f16.f32 "
        "{%0,%1,%2,%3}, {%4,%5,%6,%7}, {%8,%9}, {%0,%1,%2,%3};"
        : "+f"(c[0]), "+f"(c[1]), "+f"(c[2]), "+f"(c[3])
        : "r"(a[0]), "r"(a[1]), "r"(a[2]), "r"(a[3]), "r"(b[0]), "r"(b[1]));
}

// ================= convert kernels =================
// fp32 -> fp16 elementwise (vector4)
__global__ void convH_kernel(const float* __restrict__ X, __half* __restrict__ Y, int n4) {
    int i = blockIdx.x * blockDim.x + threadIdx.x;
    if (i >= n4) return;
    float4 x = ((const float4*)X)[i];
    __half2 h0 = __floats2half2_rn(x.x, x.y);
    __half2 h1 = __floats2half2_rn(x.z, x.w);
    uint2 o; o.x = *(uint32_t*)&h0; o.y = *(uint32_t*)&h1;
    *(uint2*)(Y + 4 * (size_t)i) = o;
}

// W [K][N] fp32 -> Bt [N][K] fp16 (tiled transpose)
__global__ __launch_bounds__(256) void convBT16_kernel(
    const float* __restrict__ W, __half* __restrict__ Bt, int K, int N) {
    __shared__ float t[32][33];
    const int tx = threadIdx.x & 31, ty = threadIdx.x >> 5;
    const int n0 = blockIdx.x * 32, k0 = blockIdx.y * 32;
#pragma unroll
    for (int j = 0; j < 32; j += 8)
        t[ty + j][tx] = W[(size_t)(k0 + ty + j) * N + n0 + tx];
    __syncthreads();
#pragma unroll
    for (int j = 0; j < 32; j += 8)
        Bt[(size_t)(n0 + ty + j) * K + k0 + tx] = __float2half(t[tx][ty + j]);
}

// V [s][d] fp32 (one kv head via blockIdx.z) -> Vt [d][s] fp16
__global__ __launch_bounds__(256) void convVT_kernel(const float* __restrict__ V,
                                                     __half* __restrict__ Vt) {
    __shared__ float t[32][33];
    const int tx = threadIdx.x & 31, ty = threadIdx.x >> 5;
    const int s0 = blockIdx.x * 32, d0 = blockIdx.y * 32, kvh = blockIdx.z;
    const float* Vh = V + (size_t)kvh * SEQ * HD;
    __half* Vth = Vt + (size_t)kvh * HD * SEQ;
#pragma unroll
    for (int j = 0; j < 32; j += 8)
        t[ty + j][tx] = Vh[(size_t)(s0 + ty + j) * HD + d0 + tx];
    __syncthreads();
#pragma unroll
    for (int j = 0; j < 32; j += 8)
        Vth[(size_t)(d0 + ty + j) * SEQ + s0 + tx] = __float2half(t[tx][ty + j]);
}

// ================= fp16 mma.sync GEMM (identical to R14 pass) =================
#define FTSZ   18432
#define FSTAGE (2 * FTSZ)
#define MGF_SMEM (2 * FSTAGE)

__device__ __forceinline__ void load_tiles16(uint32_t sbase,
    const __half* Ab, const __half* Bb, int K, int k0, int tid)
{
#pragma unroll
    for (int i = 0; i < 4; i++) {
        const int seg = i * 256 + tid;
        const int r = seg >> 3, cs = seg & 7;
        const size_t go = (size_t)r * K + k0 + cs * 8;
        const uint32_t so = r * 144 + cs * 16;
        cp16(sbase + so,        Ab + go);
        cp16(sbase + FTSZ + so, Bb + go);
    }
}

__global__ __launch_bounds__(256) void mma_gemm_f16(
    const __half* __restrict__ A, const __half* __restrict__ B,
    float* __restrict__ C, int M, int N, int K, int mode)
{
    extern __shared__ __align__(128) char smem[];
    const uint32_t sb0 = smem_u32(smem);
    const int tid  = threadIdx.x;
    const int lane = tid & 31, warp = tid >> 5;
    const int wm = warp & 3, wn = warp >> 2;
    const int bn = blockIdx.x, bm = blockIdx.y;

    const __half* Ab = A + (size_t)bm * 128 * K;
    const __half* Bb = B + (size_t)bn * 128 * K;

    float c[2][8][4];
#pragma unroll
    for (int mi = 0; mi < 2; mi++)
#pragma unroll
        for (int j = 0; j < 8; j++)
#pragma unroll
            for (int q = 0; q < 4; q++) c[mi][j][q] = 0.f;

    const int nch = K / 64;
    load_tiles16(sb0, Ab, Bb, K, 0, tid);
    CP_COMMIT();

    const int a_lrow = lane & 15;
    const int a_lcol = (lane >> 4) << 3;
    const int b_lrow = (lane & 7) + ((lane >> 4) << 3);
    const int b_lcol = ((lane >> 3) & 1) << 3;

#pragma unroll 1
    for (int ch = 0; ch < nch; ch++) {
        if (ch + 1 < nch) {
            load_tiles16(sb0 + ((ch + 1) & 1) * FSTAGE, Ab, Bb, K, (ch + 1) * 64, tid);
            CP_COMMIT();
            CP_WAIT1();
        } else {
            CP_WAIT0();
        }
        __syncthreads();

        const uint32_t sA = sb0 + (ch & 1) * FSTAGE;
        const uint32_t sB = sA + FTSZ;

#pragma unroll
        for (int kk = 0; kk < 4; kk++) {
            uint32_t a[2][4];
            const int acol = kk * 16 + a_lcol;
#pragma unroll
            for (int mi = 0; mi < 2; mi++)
                ldsm4(a[mi], sA + (uint32_t)(wm * 32 + mi * 16 + a_lrow) * 144 + acol * 2);
            const int bcol = kk * 16 + b_lcol;
#pragma unroll
            for (int ni = 0; ni < 4; ni++) {
                uint32_t b[4];
                ldsm4(b, sB + (uint32_t)(wn * 64 + ni * 16 + b_lrow) * 144 + bcol * 2);
#pragma unroll
                for (int mi = 0; mi < 2; mi++) {
                    mma16816h(c[mi][2 * ni],     a[mi], b);
                    mma16816h(c[mi][2 * ni + 1], a[mi], b + 2);
                }
            }
        }
        __syncthreads();
    }

    const int gr = lane >> 2, gc = (lane & 3) * 2;
#pragma unroll
    for (int mi = 0; mi < 2; mi++) {
#pragma unroll
        for (int j = 0; j < 8; j++) {
            const int col = bn * 128 + wn * 64 + j * 8 + gc;
#pragma unroll
            for (int hf = 0; hf < 2; hf++) {
                const int row = bm * 128 + wm * 32 + mi * 16 + gr + hf * 8;
                const float v0 = c[mi][j][2 * hf], v1 = c[mi][j][2 * hf + 1];
                if (mode == 1) {
                    const int hh = col >> 8;
                    float* dst = C + ((size_t)hh * M + row) * 256 + (col & 255);
                    dst[0] = v0; dst[1] = v1;
                } else {
                    float* dst = C + (size_t)row * N + col;
                    dst[0] = v0; dst[1] = v1;
                }
            }
        }
    }
}

// ---------------- RoPE (identical to R14 pass) ----------------
__global__ void rope_table_kernel() {
    const int s = blockIdx.x;
    const int d = threadIdx.x;
    const double inv = exp(-((double)d) * (log(10000.0) / 128.0));
    const double ang = (double)s * inv;
    const double twopi = 6.283185307179586476925286766559;
    const double k = floor(ang / twopi + 0.5);
    const float r = (float)(ang - k * twopi);
    float sv, cv;
    sincosf(r, &sv, &cv);
    g_rope[s * 128 + d] = make_float2(cv, sv);
}

__global__ void rope_apply_f16_kernel(const float* __restrict__ QKV,
                                      __half* __restrict__ Qf,
                                      __half* __restrict__ Kf) {
    const int s  = blockIdx.x;
    const int hh = blockIdx.y;
    const int d  = threadIdx.x;
    const float* p = QKV + ((size_t)hh * SEQ + s) * HD;
    __half* o = (hh < NH)
        ? Qf + ((size_t)hh * SEQ + s) * HD
        : Kf + ((size_t)(hh - NH) * SEQ + s) * HD;
    const float2 cs = g_rope[s * 128 + d];
    const float x1 = p[d];
    const float x2 = p[d + 128];
    o[d]       = __float2half(x1 * cs.x - x2 * cs.y);
    o[d + 128] = __float2half(x2 * cs.x + x1 * cs.y);
}

// ================= fp16 tensor-core flash attention =================
// BM=64 q-rows, BN=32 keys per iter (2 CTAs/SM), D=256, double-buffered K/V.
// 8 warps: wm=warp&3 -> 16 q-rows; wd=warp>>2 -> d-half for PV (S duplicated).
// V tile rows: 32 keys (64B) + 8 pad halves = 80B stride -> 16B-aligned and
// conflict-free (r*80 mod 128 cycles through 8 distinct offsets).
#define FKPAD 264
#define FVSTR 40                     // halves per V row (80 bytes)
#define FQ_OFF 0
#define FQ_SZ  (64 * FKPAD * 2)      // 33792
#define FKB_SZ (32 * FKPAD * 2)      // 16896 (32 keys x 256d + pad)
#define FVB_SZ (256 * FVSTR * 2)     // 20480 (256 d x 32 keys + pad)
#define FSTG   (FKB_SZ + FVB_SZ)     // 37376
#define FK_OFF(s) (FQ_SZ + (s) * FSTG)
#define FV_OFF(s) (FK_OFF(s) + FKB_SZ)
#define FLASH2_SMEM (FQ_SZ + 2 * FSTG)   // 108544 -> 2 CTAs/SM

__global__ __launch_bounds__(256, 2) void flash2_kernel(
    const __half* __restrict__ Qf, const __half* __restrict__ Kf,
    const __half* __restrict__ Vtf, __half* __restrict__ ctx)
{
    extern __shared__ __align__(128) char fsm[];
    const uint32_t sb = smem_u32(fsm);
    const int qb  = gridDim.x - 1 - blockIdx.x;   // heavy blocks first
    const int h   = blockIdx.y;
    const int tid = threadIdx.x, lane = tid & 31, warp = tid >> 5;
    const int wm = warp & 3, wd = warp >> 2;

    const __half* Qh = Qf + ((size_t)h * SEQ + qb * 64) * HD;
    const __half* Kh = Kf + (size_t)(h >> 1) * SEQ * HD;
    const __half* Vh = Vtf + (size_t)(h >> 1) * HD * SEQ;   // [d][s]

    // Q tile: 64 x 256 fp16
#pragma unroll
    for (int i = 0; i < 8; i++) {
        const int seg = i * 256 + tid;
        const int r = seg >> 5, c = (seg & 31) * 8;
        cp16(sb + FQ_OFF + (uint32_t)(r * FKPAD + c) * 2, Qh + (size_t)r * HD + c);
    }
    // stage 0: K keys 0..31 (32 x 256), V cols 0..31 (256 x 32)
#pragma unroll
    for (int i = 0; i < 4; i++) {
        const int seg = i * 256 + tid;
        const int r = seg >> 5, c = (seg & 31) * 8;
        cp16(sb + FK_OFF(0) + (uint32_t)(r * FKPAD + c) * 2, Kh + (size_t)r * HD + c);
    }
#pragma unroll
    for (int i = 0; i < 4; i++) {
        const int seg = i * 256 + tid;
        const int r = seg >> 2, c = (seg & 3) * 8;
        cp16(sb + FV_OFF(0) + (uint32_t)(r * FVSTR + c) * 2, Vh + (size_t)r * SEQ + c);
    }
    CP_COMMIT();

    float O[64];
#pragma unroll
    for (int i = 0; i < 64; i++) O[i] = 0.f;
    float mi0 = -1e30f, mi1 = -1e30f, li0 = 0.f, li1 = 0.f;

    const int a_lrow = lane & 15;
    const int a_lcol = (lane >> 4) << 3;
    const int b_lrow = (lane & 7) + ((lane >> 4) << 3);
    const int b_lcol = ((lane >> 3) & 1) << 3;

    const int nkb = 2 * qb + 2;
#pragma unroll 1
    for (int kb = 0; kb < nkb; kb++) {
        if (kb + 1 < nkb) {
            const int st = (kb + 1) & 1;
            const __half* Kn = Kh + (size_t)(kb + 1) * 32 * HD;
#pragma unroll
            for (int i = 0; i < 4; i++) {
                const int seg = i * 256 + tid;
                const int r = seg >> 5, c = (seg & 31) * 8;
                cp16(sb + FK_OFF(st) + (uint32_t)(r * FKPAD + c) * 2, Kn + (size_t)r * HD + c);
            }
#pragma unroll
            for (int i = 0; i < 4; i++) {
                const int seg = i * 256 + tid;
                const int r = seg >> 2, c = (seg & 3) * 8;
                cp16(sb + FV_OFF(st) + (uint32_t)(r * FVSTR + c) * 2,
                     Vh + (size_t)r * SEQ + (kb + 1) * 32 + c);
            }
            CP_COMMIT();
            CP_WAIT1();
        } else {
            CP_WAIT0();
        }
        __syncthreads();

        const uint32_t sK = sb + FK_OFF(kb & 1);
        const uint32_t sV = sb + FV_OFF(kb & 1);

        // ---- S = Q K^T : 16 rows x 32 keys ----
        float s[4][4];
#pragma unroll
        for (int j = 0; j < 4; j++)
#pragma unroll
            for (int q = 0; q < 4; q++) s[j][q] = 0.f;

#pragma unroll
        for (int ks = 0; ks < 16; ks++) {
            uint32_t a[4];
            ldsm4(a, sb + FQ_OFF + (uint32_t)((wm * 16 + a_lrow) * FKPAD + ks * 16 + a_lcol) * 2);
#pragma unroll
            for (int nj = 0; nj < 2; nj++) {
                uint32_t b[4];
                ldsm4(b, sK + (uint32_t)((nj * 16 + b_lrow) * FKPAD + ks * 16 + b_lcol) * 2);
                mma16816h(s[2 * nj],     a, b);
                mma16816h(s[2 * nj + 1], a, b + 2);
            }
        }

        // scale + softcap: tanh(y) = 1 - 2/(e^{2y}+1)
#pragma unroll
        for (int j = 0; j < 4; j++)
#pragma unroll
            for (int q = 0; q < 4; q++) {
                const float e = __expf(s[j][q] * 0.0025f);
                s[j][q] = 50.f - 100.f * __fdividef(1.f, e + 1.f);
            }
        // causal mask (global indices); active only for the last two key-blocks
        if (kb >= 2 * qb) {
            const int rl = qb * 64 + wm * 16 + (lane >> 2);
            const int cl = kb * 32 + (lane & 3) * 2;
#pragma unroll
            for (int j = 0; j < 4; j++) {
                const int c0 = cl + j * 8;
                if (c0     > rl)     s[j][0] = -1e30f;
                if (c0 + 1 > rl)     s[j][1] = -1e30f;
                if (c0     > rl + 8) s[j][2] = -1e30f;
                if (c0 + 1 > rl + 8) s[j][3] = -1e30f;
            }
        }

        // ---- online softmax (rows lane>>2 and +8) ----
        float m0 = -1e30f, m1 = -1e30f;
#pragma unroll
        for (int j = 0; j < 4; j++) {
            m0 = fmaxf(m0, fmaxf(s[j][0], s[j][1]));
            m1 = fmaxf(m1, fmaxf(s[j][2], s[j][3]));
        }
        m0 = fmaxf(m0, __shfl_xor_sync(0xffffffffu, m0, 1));
        m0 = fmaxf(m0, __shfl_xor_sync(0xffffffffu, m0, 2));
        m1 = fmaxf(m1, __shfl_xor_sync(0xffffffffu, m1, 1));
        m1 = fmaxf(m1, __shfl_xor_sync(0xffffffffu, m1, 2));
        const float nm0 = fmaxf(mi0, m0), nm1 = fmaxf(mi1, m1);
        const float corr0 = __expf(mi0 - nm0), corr1 = __expf(mi1 - nm1);
        float rs0 = 0.f, rs1 = 0.f;
#pragma unroll
        for (int j = 0; j < 4; j++) {
            s[j][0] = __expf(s[j][0] - nm0);
            s[j][1] = __expf(s[j][1] - nm0);
            s[j][2] = __expf(s[j][2] - nm1);
            s[j][3] = __expf(s[j][3] - nm1);
            rs0 += s[j][0] + s[j][1];
            rs1 += s[j][2] + s[j][3];
        }
        rs0 += __shfl_xor_sync(0xffffffffu, rs0, 1);
        rs0 += __shfl_xor_sync(0xffffffffu, rs0, 2);
        rs1 += __shfl_xor_sync(0xffffffffu, rs1, 1);
        rs1 += __shfl_xor_sync(0xffffffffu, rs1, 2);
        li0 = li0 * corr0 + rs0;  mi0 = nm0;
        li1 = li1 * corr1 + rs1;  mi1 = nm1;

        // pack P into mma A fragments
        uint32_t pa[2][4];
#pragma unroll
        for (int g = 0; g < 2; g++) {
            __half2 t0 = __floats2half2_rn(s[2 * g][0],     s[2 * g][1]);
            __half2 t1 = __floats2half2_rn(s[2 * g][2],     s[2 * g][3]);
            __half2 t2 = __floats2half2_rn(s[2 * g + 1][0], s[2 * g + 1][1]);
            __half2 t3 = __floats2half2_rn(s[2 * g + 1][2], s[2 * g + 1][3]);
            pa[g][0] = *(uint32_t*)&t0;
            pa[g][1] = *(uint32_t*)&t1;
            pa[g][2] = *(uint32_t*)&t2;
            pa[g][3] = *(uint32_t*)&t3;
        }

        // rescale O, then O += P * V
#pragma unroll
        for (int dn = 0; dn < 8; dn++) {
            O[dn * 8 + 0] *= corr0; O[dn * 8 + 1] *= corr0;
            O[dn * 8 + 2] *= corr1; O[dn * 8 + 3] *= corr1;
            O[dn * 8 + 4] *= corr0; O[dn * 8 + 5] *= corr0;
            O[dn * 8 + 6] *= corr1; O[dn * 8 + 7] *= corr1;
        }
#pragma unroll
        for (int dn = 0; dn < 8; dn++) {
#pragma unroll
            for (int g = 0; g < 2; g++) {
                uint32_t b[4];
                ldsm4(b, sV + (uint32_t)((wd * 128 + dn * 16 + b_lrow) * FVSTR + g * 16 + b_lcol) * 2);
                mma16816h(O + dn * 8,     pa[g], b);
                mma16816h(O + dn * 8 + 4, pa[g], b + 2);
            }
        }
        __syncthreads();
    }

    // epilogue: write fp16 ctx directly (row stride NH*HD = 2048)
    const float inv0 = 1.f / li0, inv1 = 1.f / li1;
    const int row0 = qb * 64 + wm * 16 + (lane >> 2);
    const int colb = h * 256 + wd * 128 + (lane & 3) * 2;
#pragma unroll
    for (int dn = 0; dn < 8; dn++) {
        const int c0 = colb + dn * 16;
        __half* d0 = ctx + (size_t)row0 * (NH * HD) + c0;
        __half* d1 = ctx + (size_t)(row0 + 8) * (NH * HD) + c0;
        *(__half2*)(d0)     = __floats2half2_rn(O[dn * 8 + 0] * inv0, O[dn * 8 + 1] * inv0);
        *(__half2*)(d1)     = __floats2half2_rn(O[dn * 8 + 2] * inv1, O[dn * 8 + 3] * inv1);
        *(__half2*)(d0 + 8) = __floats2half2_rn(O[dn * 8 + 4] * inv0, O[dn * 8 + 5] * inv0);
        *(__half2*)(d1 + 8) = __floats2half2_rn(O[dn * 8 + 6] * inv1, O[dn * 8 + 7] * inv1);
    }
}

// ---------------- launcher ----------------
extern "C" void kernel_launch(void* const* d_in, const int* in_sizes, int n_in,
                              void* d_out, int out_size) {
    const float* H  = (const float*)d_in[0];
    const float* Wq = (const float*)d_in[1];
    const float* Wk = (const float*)d_in[2];
    const float* Wv = (const float*)d_in[3];
    const float* Wo = (const float*)d_in[4];
    float* out = (float*)d_out;

    float* QKVp;
    __half *Afp, *Bfp, *Qfp, *Kfp, *Vtp;
    cudaGetSymbolAddress((void**)&QKVp, g_QKV);
    cudaGetSymbolAddress((void**)&Afp, g_Af);
    cudaGetSymbolAddress((void**)&Bfp, g_Bf);
    cudaGetSymbolAddress((void**)&Qfp, g_Qf);
    cudaGetSymbolAddress((void**)&Kfp, g_Kf);
    cudaGetSymbolAddress((void**)&Vtp, g_Vt);

    cudaFuncSetAttribute(mma_gemm_f16,
                         cudaFuncAttributeMaxDynamicSharedMemorySize, MGF_SMEM);
    cudaFuncSetAttribute(flash2_kernel,
                         cudaFuncAttributeMaxDynamicSharedMemorySize, FLASH2_SMEM);

    // H -> fp16
    convH_kernel<<<(SEQ * HID / 4) / 256, 256>>>(H, Afp, SEQ * HID / 4);

    // [Wq|Wk|Wv]^T -> fp16 [4096][2304]
    convBT16_kernel<<<dim3(2048 / 32, HID / 32), 256>>>(Wq, Bfp, HID, 2048);
    convBT16_kernel<<<dim3(1024 / 32, HID / 32), 256>>>(Wk, Bfp + (size_t)2048 * HID, HID, 1024);
    convBT16_kernel<<<dim3(1024 / 32, HID / 32), 256>>>(Wv, Bfp + (size_t)3072 * HID, HID, 1024);

    // fused QKV projection: [4096,2304] x [2304,4096] -> head-split 16 heads
    mma_gemm_f16<<<dim3(4096 / 128, SEQ / 128), 256, MGF_SMEM>>>(
        Afp, Bfp, QKVp, SEQ, 4096, HID, 1);

    // RoPE (table + fused apply-and-convert to fp16)
    rope_table_kernel<<<SEQ, 128>>>();
    rope_apply_f16_kernel<<<dim3(SEQ, NH + NKV), 128>>>(QKVp, Qfp, Kfp);

    // V -> fp16 transposed
    convVT_kernel<<<dim3(SEQ / 32, HD / 32, NKV), 256>>>(
        QKVp + (size_t)12 * SEQ * HD, Vtp);

    // Attention -> writes fp16 ctx into g_Af (Hf already consumed by QKV GEMM)
    flash2_kernel<<<dim3(SEQ / 64, NH), 256, FLASH2_SMEM>>>(Qfp, Kfp, Vtp, Afp);

    // Output projection: ctx[4096,2048] @ Wo[2048,2304]
    convBT16_kernel<<<dim3(HID / 32, 2048 / 32), 256>>>(Wo, Bfp, 2048, HID);
    mma_gemm_f16<<<dim3(HID / 128, SEQ / 128), 256, MGF_SMEM>>>(
        Afp, Bfp, out, SEQ, HID, 2048, 0);
}